// round 2
// baseline (speedup 1.0000x reference)
#include <cuda_runtime.h>

// Problem constants (fixed shapes for this problem)
#define Bc 2
#define Tc 2048
#define Cc 1024
#define Hc 16
#define Dc 64

// Scratch: q,k,v in [B,H,T,D]; y (attention out) in [B,T,C]
__device__ float g_q[Bc * Hc * Tc * Dc];
__device__ float g_k[Bc * Hc * Tc * Dc];
__device__ float g_v[Bc * Hc * Tc * Dc];
__device__ float g_y[Bc * Tc * Cc];

// ---------------------------------------------------------------------------
// GEMM: out = X @ W^T + bias      X:[M,K] row-major, W:[N,K] row-major
// M = Bc*Tc = 4096, N = K = Cc = 1024.
// 64x64 tile, 256 threads, 4x4 per-thread micro-tile, BK=16.
// SPLIT=true  -> write to [B,H,T,D] layout (for q/k/v scratch)
// SPLIT=false -> write to [M,N] row-major (y proj / final out)
// ---------------------------------------------------------------------------
template <bool SPLIT>
__global__ __launch_bounds__(256) void gemm64(const float* __restrict__ X,
                                              const float* __restrict__ W,
                                              const float* __restrict__ bias,
                                              float* __restrict__ out) {
    __shared__ float As[16][68];
    __shared__ float Bs[16][68];

    const int tid = threadIdx.x;
    const int tx = tid & 15;
    const int ty = tid >> 4;
    const int m0 = blockIdx.y * 64;
    const int n0 = blockIdx.x * 64;

    float acc[4][4] = {};

    for (int k0 = 0; k0 < Cc; k0 += 16) {
#pragma unroll
        for (int i = 0; i < 4; i++) {
            int idx = tid + i * 256;          // 0..1023
            int kk = idx & 15;
            int r = idx >> 4;                 // 0..63
            As[kk][r] = X[(size_t)(m0 + r) * Cc + k0 + kk];
            Bs[kk][r] = W[(size_t)(n0 + r) * Cc + k0 + kk];
        }
        __syncthreads();

#pragma unroll
        for (int kk = 0; kk < 16; kk++) {
            float4 a4 = *(const float4*)&As[kk][ty * 4];
            float4 b4 = *(const float4*)&Bs[kk][tx * 4];
            float av[4] = {a4.x, a4.y, a4.z, a4.w};
            float bv[4] = {b4.x, b4.y, b4.z, b4.w};
#pragma unroll
            for (int r = 0; r < 4; r++)
#pragma unroll
                for (int c = 0; c < 4; c++) acc[r][c] += av[r] * bv[c];
        }
        __syncthreads();
    }

#pragma unroll
    for (int r = 0; r < 4; r++) {
        int m = m0 + ty * 4 + r;
#pragma unroll
        for (int c = 0; c < 4; c++) {
            int n = n0 + tx * 4 + c;
            float val = acc[r][c] + bias[n];
            if (SPLIT) {
                int b = m >> 11;      // m / Tc
                int t = m & 2047;     // m % Tc
                int h = n >> 6;       // n / Dc
                int d = n & 63;       // n % Dc
                out[((size_t)((b * Hc + h) * Tc + t)) * Dc + d] = val;
            } else {
                out[(size_t)m * Cc + n] = val;
            }
        }
    }
}

// ---------------------------------------------------------------------------
// Causal flash attention, fp32, online softmax.
// Grid: (T/64, B*H). Block: 256 threads (16x16), 4x4 per-thread tiles.
// smem: Qt [D][68] d-major, Kt [D][68] d-major, Vs [N][68], St [N][68].
// ---------------------------------------------------------------------------
__global__ __launch_bounds__(256) void attn64(const float* __restrict__ Q,
                                              const float* __restrict__ K,
                                              const float* __restrict__ V,
                                              float* __restrict__ Y) {
    extern __shared__ float smem[];
    float* Qt = smem;               // [64][68]  Qt[d][m]
    float* Kt = Qt + 64 * 68;       // [64][68]  Kt[d][n]
    float* Vs = Kt + 64 * 68;       // [64][68]  Vs[n][d]
    float* St = Vs + 64 * 68;       // [64][68]  St[n][m]

    const int tid = threadIdx.x;
    const int tx = tid & 15;
    const int ty = tid >> 4;
    const int bh = blockIdx.y;          // 0..31
    const int m0 = blockIdx.x * 64;

    const float* q = Q + (size_t)bh * Tc * Dc;
    const float* k = K + (size_t)bh * Tc * Dc;
    const float* v = V + (size_t)bh * Tc * Dc;

    // Load Q tile transposed (coalesced global reads along d)
#pragma unroll
    for (int i = 0; i < 16; i++) {
        int idx = tid + i * 256;        // 0..4095
        int d = idx & 63;
        int t = idx >> 6;
        Qt[d * 68 + t] = q[(size_t)(m0 + t) * Dc + d];
    }

    float acc[4][4] = {};
    float row_max[4], row_sum[4];
#pragma unroll
    for (int r = 0; r < 4; r++) { row_max[r] = -1e30f; row_sum[r] = 0.0f; }

    const float scale = 0.125f;     // 1/sqrt(64)

    for (int n0 = 0; n0 <= m0; n0 += 64) {
        __syncthreads();   // previous iteration's readers of Kt/Vs/St done
#pragma unroll
        for (int i = 0; i < 16; i++) {
            int idx = tid + i * 256;
            int d = idx & 63;
            int t = idx >> 6;
            float kv = k[(size_t)(n0 + t) * Dc + d];
            float vv = v[(size_t)(n0 + t) * Dc + d];
            Kt[d * 68 + t] = kv;   // transposed
            Vs[t * 68 + d] = vv;   // direct
        }
        __syncthreads();

        // Phase 1: S = Q K^T
        float s[4][4] = {};
#pragma unroll 8
        for (int d = 0; d < 64; d++) {
            float4 a4 = *(const float4*)&Qt[d * 68 + ty * 4];
            float4 b4 = *(const float4*)&Kt[d * 68 + tx * 4];
            float av[4] = {a4.x, a4.y, a4.z, a4.w};
            float bv[4] = {b4.x, b4.y, b4.z, b4.w};
#pragma unroll
            for (int r = 0; r < 4; r++)
#pragma unroll
                for (int c = 0; c < 4; c++) s[r][c] += av[r] * bv[c];
        }

        // scale + causal mask (only the diagonal tile needs masking)
        if (n0 == m0) {
#pragma unroll
            for (int r = 0; r < 4; r++)
#pragma unroll
                for (int c = 0; c < 4; c++) {
                    if (tx * 4 + c > ty * 4 + r) s[r][c] = -1e30f;
                    else s[r][c] *= scale;
                }
        } else {
#pragma unroll
            for (int r = 0; r < 4; r++)
#pragma unroll
                for (int c = 0; c < 4; c++) s[r][c] *= scale;
        }

        // Online softmax per row (reduce across the 16 threads sharing ty;
        // those are a contiguous, 16-aligned lane group -> shfl_xor o<16 stays inside)
#pragma unroll
        for (int r = 0; r < 4; r++) {
            float tm = fmaxf(fmaxf(s[r][0], s[r][1]), fmaxf(s[r][2], s[r][3]));
#pragma unroll
            for (int o = 8; o >= 1; o >>= 1)
                tm = fmaxf(tm, __shfl_xor_sync(0xffffffffu, tm, o));
            float nm = fmaxf(row_max[r], tm);
            float corr = __expf(row_max[r] - nm);
            row_max[r] = nm;
            float ts = 0.0f;
#pragma unroll
            for (int c = 0; c < 4; c++) {
                s[r][c] = __expf(s[r][c] - nm);
                ts += s[r][c];
            }
#pragma unroll
            for (int o = 8; o >= 1; o >>= 1)
                ts += __shfl_xor_sync(0xffffffffu, ts, o);
            row_sum[r] = row_sum[r] * corr + ts;
#pragma unroll
            for (int c = 0; c < 4; c++) acc[r][c] *= corr;
        }

        // Stage P transposed: St[n][m]
#pragma unroll
        for (int r = 0; r < 4; r++)
#pragma unroll
            for (int c = 0; c < 4; c++)
                St[(tx * 4 + c) * 68 + ty * 4 + r] = s[r][c];
        __syncthreads();

        // Phase 2: O += P @ V
#pragma unroll 8
        for (int n = 0; n < 64; n++) {
            float4 p4 = *(const float4*)&St[n * 68 + ty * 4];
            float4 w4 = *(const float4*)&Vs[n * 68 + tx * 4];
            float pv[4] = {p4.x, p4.y, p4.z, p4.w};
            float wv[4] = {w4.x, w4.y, w4.z, w4.w};
#pragma unroll
            for (int r = 0; r < 4; r++)
#pragma unroll
                for (int c = 0; c < 4; c++) acc[r][c] += pv[r] * wv[c];
        }
    }

    // Epilogue: normalize, write y in [B,T,C] layout (C index = h*64 + d)
    const int b = bh >> 4;
    const int h = bh & 15;
#pragma unroll
    for (int r = 0; r < 4; r++) {
        float inv = 1.0f / row_sum[r];
        int t = m0 + ty * 4 + r;
#pragma unroll
        for (int c = 0; c < 4; c++) {
            Y[((size_t)(b * Tc + t)) * Cc + h * Dc + tx * 4 + c] = acc[r][c] * inv;
        }
    }
}

// ---------------------------------------------------------------------------
extern "C" void kernel_launch(void* const* d_in, const int* in_sizes, int n_in,
                              void* d_out, int out_size) {
    const float* x  = (const float*)d_in[0];
    const float* Wk = (const float*)d_in[1];
    const float* bk = (const float*)d_in[2];
    const float* Wq = (const float*)d_in[3];
    const float* bq = (const float*)d_in[4];
    const float* Wv = (const float*)d_in[5];
    const float* bv = (const float*)d_in[6];
    const float* Wp = (const float*)d_in[7];
    const float* bp = (const float*)d_in[8];
    float* out = (float*)d_out;

    float *qp, *kp, *vp, *yp;
    cudaGetSymbolAddress((void**)&qp, g_q);
    cudaGetSymbolAddress((void**)&kp, g_k);
    cudaGetSymbolAddress((void**)&vp, g_v);
    cudaGetSymbolAddress((void**)&yp, g_y);

    const int smem_attn = 4 * 64 * 68 * (int)sizeof(float);   // 69632 B
    cudaFuncSetAttribute(attn64, cudaFuncAttributeMaxDynamicSharedMemorySize,
                         smem_attn);

    dim3 gemm_grid(Cc / 64, (Bc * Tc) / 64);   // (16, 64)
    gemm64<true><<<gemm_grid, 256>>>(x, Wq, bq, qp);
    gemm64<true><<<gemm_grid, 256>>>(x, Wk, bk, kp);
    gemm64<true><<<gemm_grid, 256>>>(x, Wv, bv, vp);

    dim3 attn_grid(Tc / 64, Bc * Hc);          // (32, 32)
    attn64<<<attn_grid, 256, smem_attn>>>(qp, kp, vp, yp);

    gemm64<false><<<gemm_grid, 256>>>(yp, Wp, bp, out);
}

// round 7
// speedup vs baseline: 2.7627x; 2.7627x over previous
#include <cuda_runtime.h>
#include <cuda_bf16.h>
#include <cstdint>

// Problem constants
#define Bc 2
#define Tc 2048
#define Cc 1024
#define Hc 16
#define Dc 64
#define Mtot 4096
#define BHc 32

// ---------------------------------------------------------------------------
// Scratch (__device__ globals; 16B-aligned for cp.async / vector access)
// ---------------------------------------------------------------------------
__device__ __align__(256) __nv_bfloat16 g_xh[Mtot * Cc];
__device__ __align__(256) __nv_bfloat16 g_xl[Mtot * Cc];
__device__ __align__(256) __nv_bfloat16 g_qh[BHc * Tc * Dc];
__device__ __align__(256) __nv_bfloat16 g_ql[BHc * Tc * Dc];
__device__ __align__(256) __nv_bfloat16 g_kh[BHc * Tc * Dc];
__device__ __align__(256) __nv_bfloat16 g_kl[BHc * Tc * Dc];
__device__ __align__(256) __nv_bfloat16 g_vh[BHc * Tc * Dc];
__device__ __align__(256) __nv_bfloat16 g_vl[BHc * Tc * Dc];
__device__ __align__(256) __nv_bfloat16 g_yh[Mtot * Cc];
__device__ __align__(256) __nv_bfloat16 g_yl[Mtot * Cc];
__device__ __align__(256) __nv_bfloat16 g_wqh[Cc * Cc];
__device__ __align__(256) __nv_bfloat16 g_wql[Cc * Cc];
__device__ __align__(256) __nv_bfloat16 g_wkh[Cc * Cc];
__device__ __align__(256) __nv_bfloat16 g_wkl[Cc * Cc];
__device__ __align__(256) __nv_bfloat16 g_wvh[Cc * Cc];
__device__ __align__(256) __nv_bfloat16 g_wvl[Cc * Cc];
__device__ __align__(256) __nv_bfloat16 g_wph[Cc * Cc];
__device__ __align__(256) __nv_bfloat16 g_wpl[Cc * Cc];

// ---------------------------------------------------------------------------
// Baseline-PTX helpers (no arch-specific 'a' features!)
// ---------------------------------------------------------------------------
__device__ __forceinline__ uint32_t cvta_s(const void* p) {
    return (uint32_t)__cvta_generic_to_shared(p);
}

__device__ __forceinline__ void ldsm4(uint32_t a, uint32_t& r0, uint32_t& r1,
                                      uint32_t& r2, uint32_t& r3) {
    asm volatile("ldmatrix.sync.aligned.m8n8.x4.shared.b16 {%0,%1,%2,%3}, [%4];"
                 : "=r"(r0), "=r"(r1), "=r"(r2), "=r"(r3) : "r"(a));
}
__device__ __forceinline__ void ldsm2t(uint32_t a, uint32_t& r0, uint32_t& r1) {
    asm volatile("ldmatrix.sync.aligned.m8n8.x2.trans.shared.b16 {%0,%1}, [%2];"
                 : "=r"(r0), "=r"(r1) : "r"(a));
}
__device__ __forceinline__ void mma16816(float* d, const uint32_t* a,
                                         const uint32_t* b) {
    asm volatile(
        "mma.sync.aligned.m16n8k16.row.col.f32.bf16.bf16.f32 "
        "{%0,%1,%2,%3}, {%4,%5,%6,%7}, {%8,%9}, {%0,%1,%2,%3};"
        : "+f"(d[0]), "+f"(d[1]), "+f"(d[2]), "+f"(d[3])
        : "r"(a[0]), "r"(a[1]), "r"(a[2]), "r"(a[3]), "r"(b[0]), "r"(b[1]));
}
#define CPA16(s, g) \
    asm volatile("cp.async.cg.shared.global [%0], [%1], 16;" :: "r"(s), "l"(g))
#define CPCOMMIT() asm volatile("cp.async.commit_group;" ::: "memory")
#define CPWAIT(n)  asm volatile("cp.async.wait_group %0;" :: "n"(n) : "memory")

__device__ __forceinline__ uint32_t pack_bf(__nv_bfloat16 a, __nv_bfloat16 b) {
    __nv_bfloat162 t = __halves2bfloat162(a, b);
    return *reinterpret_cast<uint32_t*>(&t);
}
// (even, odd) fp32 pair -> packed bf16 hi frag + lo frag
__device__ __forceinline__ void split_pack(float e, float o, uint32_t& hi,
                                           uint32_t& lo) {
    __nv_bfloat16 he = __float2bfloat16_rn(e);
    __nv_bfloat16 ho = __float2bfloat16_rn(o);
    __nv_bfloat16 le = __float2bfloat16_rn(e - __bfloat162float(he));
    __nv_bfloat16 lo_ = __float2bfloat16_rn(o - __bfloat162float(ho));
    hi = pack_bf(he, ho);
    lo = pack_bf(le, lo_);
}

// ---------------------------------------------------------------------------
// fp32 -> (hi, lo) bf16 split
// ---------------------------------------------------------------------------
__global__ __launch_bounds__(256) void split_bf16(const float* __restrict__ src,
                                                  __nv_bfloat16* __restrict__ hi,
                                                  __nv_bfloat16* __restrict__ lo) {
    int i = blockIdx.x * blockDim.x + threadIdx.x;
    float4 v = ((const float4*)src)[i];
    __nv_bfloat16 h0 = __float2bfloat16_rn(v.x);
    __nv_bfloat16 h1 = __float2bfloat16_rn(v.y);
    __nv_bfloat16 h2 = __float2bfloat16_rn(v.z);
    __nv_bfloat16 h3 = __float2bfloat16_rn(v.w);
    __nv_bfloat16 l0 = __float2bfloat16_rn(v.x - __bfloat162float(h0));
    __nv_bfloat16 l1 = __float2bfloat16_rn(v.y - __bfloat162float(h1));
    __nv_bfloat16 l2 = __float2bfloat16_rn(v.z - __bfloat162float(h2));
    __nv_bfloat16 l3 = __float2bfloat16_rn(v.w - __bfloat162float(h3));
    ((__nv_bfloat162*)hi)[2 * i]     = __halves2bfloat162(h0, h1);
    ((__nv_bfloat162*)hi)[2 * i + 1] = __halves2bfloat162(h2, h3);
    ((__nv_bfloat162*)lo)[2 * i]     = __halves2bfloat162(l0, l1);
    ((__nv_bfloat162*)lo)[2 * i + 1] = __halves2bfloat162(l2, l3);
}

// ---------------------------------------------------------------------------
// GEMM via mma.sync: out = (Ah+Al) @ (Bh+Bl)^T + bias
// A [4096 x 1024], B [1024 x 1024] (row = out-feature, K contiguous).
// CTA 128x128, 8 warps (warp tile 32x64), BK=32, double-buffered cp.async.
// MODE 0: bf16 hi/lo out into [B,H,T,D] (QKV).  MODE 1: fp32 out [M,C].
// ---------------------------------------------------------------------------
#define SRB 80u            // smem row stride bytes (40 bf16; conflict-free ldsm)
#define MATB (128u * SRB)  // 10240 B per matrix tile
#define STAGEB (4u * MATB) // Ah, Al, Bh, Bl
#define GEMM_SMEM (2u * STAGEB)

__device__ __forceinline__ void gemm_load_stage(
    uint32_t base, int tid, int m0, int n0, int k0,
    const __nv_bfloat16* __restrict__ Ah, const __nv_bfloat16* __restrict__ Al,
    const __nv_bfloat16* __restrict__ Bh, const __nv_bfloat16* __restrict__ Bl) {
#pragma unroll
    for (int it = 0; it < 2; it++) {
        int idx = tid + it * 256;
        int row = idx >> 2, seg = idx & 3;
        uint32_t so = (uint32_t)row * SRB + (uint32_t)seg * 16u;
        size_t ga = (size_t)(m0 + row) * Cc + k0 + seg * 8;
        size_t gb = (size_t)(n0 + row) * Cc + k0 + seg * 8;
        CPA16(base + so, Ah + ga);
        CPA16(base + MATB + so, Al + ga);
        CPA16(base + 2u * MATB + so, Bh + gb);
        CPA16(base + 3u * MATB + so, Bl + gb);
    }
}

template <int MODE>
__global__ __launch_bounds__(256) void gemm_mma(
    const __nv_bfloat16* __restrict__ Ah, const __nv_bfloat16* __restrict__ Al,
    const __nv_bfloat16* __restrict__ Bh, const __nv_bfloat16* __restrict__ Bl,
    const float* __restrict__ bias,
    void* __restrict__ outH, __nv_bfloat16* __restrict__ outL) {
    extern __shared__ __align__(16) char smg[];
    const uint32_t sb = cvta_s(smg);
    const int tid = threadIdx.x, lane = tid & 31, wid = tid >> 5;
    const int wm = wid & 3, wn = wid >> 2;
    const int m0 = blockIdx.y * 128, n0 = blockIdx.x * 128;

    float acc[2][8][4];
#pragma unroll
    for (int i = 0; i < 2; i++)
#pragma unroll
        for (int j = 0; j < 8; j++)
#pragma unroll
            for (int k = 0; k < 4; k++) acc[i][j][k] = 0.0f;

    gemm_load_stage(sb, tid, m0, n0, 0, Ah, Al, Bh, Bl);
    CPCOMMIT();

    const int arow = wm * 32 + (lane & 15);
    const int akof = (lane >> 4) << 3;
    const int brow = (lane & 7) + ((lane & 16) >> 1);
    const int bkof = lane & 8;

    for (int kt = 0; kt < Cc / 32; kt++) {
        if (kt + 1 < Cc / 32) {
            gemm_load_stage(sb + (uint32_t)((kt + 1) & 1) * STAGEB, tid, m0, n0,
                            (kt + 1) * 32, Ah, Al, Bh, Bl);
            CPCOMMIT();
            CPWAIT(1);
        } else {
            CPWAIT(0);
        }
        __syncthreads();
        const uint32_t base = sb + (uint32_t)(kt & 1) * STAGEB;
#pragma unroll
        for (int ks = 0; ks < 2; ks++) {
            uint32_t ah[2][4], al[2][4];
            const uint32_t acb = (uint32_t)(ks * 16 + akof) * 2u;
#pragma unroll
            for (int mf = 0; mf < 2; mf++) {
                uint32_t ao = (uint32_t)(arow + mf * 16) * SRB + acb;
                ldsm4(base + ao, ah[mf][0], ah[mf][1], ah[mf][2], ah[mf][3]);
                ldsm4(base + MATB + ao, al[mf][0], al[mf][1], al[mf][2], al[mf][3]);
            }
            uint32_t bh[4][4], bl[4][4];
            const uint32_t bcb = (uint32_t)(ks * 16 + bkof) * 2u;
#pragma unroll
            for (int ng = 0; ng < 4; ng++) {
                uint32_t bo = (uint32_t)(wn * 64 + ng * 16 + brow) * SRB + bcb;
                ldsm4(base + 2u * MATB + bo, bh[ng][0], bh[ng][1], bh[ng][2], bh[ng][3]);
                ldsm4(base + 3u * MATB + bo, bl[ng][0], bl[ng][1], bl[ng][2], bl[ng][3]);
            }
#pragma unroll
            for (int mf = 0; mf < 2; mf++)
#pragma unroll
                for (int nf = 0; nf < 8; nf++) {
                    uint32_t fh[2] = {bh[nf >> 1][(nf & 1) * 2],
                                      bh[nf >> 1][(nf & 1) * 2 + 1]};
                    uint32_t fl[2] = {bl[nf >> 1][(nf & 1) * 2],
                                      bl[nf >> 1][(nf & 1) * 2 + 1]};
                    mma16816(acc[mf][nf], ah[mf], fh);
                    mma16816(acc[mf][nf], ah[mf], fl);
                    mma16816(acc[mf][nf], al[mf], fh);
                }
        }
        __syncthreads();
    }

    // Epilogue
#pragma unroll
    for (int mf = 0; mf < 2; mf++) {
        int mg0 = m0 + wm * 32 + mf * 16 + (lane >> 2);
#pragma unroll
        for (int nf = 0; nf < 8; nf++) {
            int ng = n0 + wn * 64 + nf * 8 + (lane & 3) * 2;
            float b0v = bias[ng], b1v = bias[ng + 1];
#pragma unroll
            for (int half = 0; half < 2; half++) {
                int m = mg0 + half * 8;
                float v0 = acc[mf][nf][half * 2] + b0v;
                float v1 = acc[mf][nf][half * 2 + 1] + b1v;
                if (MODE == 0) {
                    int bb = m >> 11, t = m & 2047, h = ng >> 6, d = ng & 63;
                    size_t o = (((size_t)(bb * Hc + h)) * Tc + t) * Dc + d;
                    uint32_t hiw, low;
                    split_pack(v0, v1, hiw, low);
                    *(uint32_t*)((__nv_bfloat16*)outH + o) = hiw;
                    *(uint32_t*)(outL + o) = low;
                } else {
                    float2 v = make_float2(v0, v1);
                    *(float2*)((float*)outH + (size_t)m * Cc + ng) = v;
                }
            }
        }
    }
}

// ---------------------------------------------------------------------------
// Flash attention via mma.sync. Grid (T/64, B*H). 128 threads (4 warps,
// each warp owns 16 query rows). Q frags resident; K/V tiles 64x64 hi/lo.
// ---------------------------------------------------------------------------
#define ASR 144u                 // smem row stride bytes (72 bf16)
#define KH_OFF 0u
#define KL_OFF 9216u
#define VH_OFF 18432u
#define VL_OFF 27648u
#define ATTN_SMEM 36864u

__global__ __launch_bounds__(128) void attn_mma(
    const __nv_bfloat16* __restrict__ Qh, const __nv_bfloat16* __restrict__ Ql,
    const __nv_bfloat16* __restrict__ Kh, const __nv_bfloat16* __restrict__ Kl,
    const __nv_bfloat16* __restrict__ Vh, const __nv_bfloat16* __restrict__ Vl,
    __nv_bfloat16* __restrict__ Yh, __nv_bfloat16* __restrict__ Yl) {
    extern __shared__ __align__(16) char sma[];
    const uint32_t sb = cvta_s(sma);
    const int tid = threadIdx.x, lane = tid & 31, wid = tid >> 5;
    const int bh_i = blockIdx.y;
    const int m0 = blockIdx.x * 64;
    const size_t hb = (size_t)bh_i * Tc * Dc;

    // ---- Stage Q (hi->KH region, lo->KL region), pull frags to registers ----
#pragma unroll
    for (int it = 0; it < 4; it++) {
        int idx = tid + it * 128;
        int row = idx >> 3, seg = idx & 7;
        uint32_t so = (uint32_t)row * ASR + (uint32_t)seg * 16u;
        size_t g = hb + (size_t)(m0 + row) * Dc + seg * 8;
        CPA16(sb + KH_OFF + so, Qh + g);
        CPA16(sb + KL_OFF + so, Ql + g);
    }
    CPCOMMIT();
    CPWAIT(0);
    __syncthreads();

    uint32_t qfh[4][4], qfl[4][4];
    {
        const int arow = wid * 16 + (lane & 15);
        const int akof = (lane >> 4) << 3;
#pragma unroll
        for (int kf = 0; kf < 4; kf++) {
            uint32_t ao = (uint32_t)arow * ASR + (uint32_t)(kf * 16 + akof) * 2u;
            ldsm4(sb + KH_OFF + ao, qfh[kf][0], qfh[kf][1], qfh[kf][2], qfh[kf][3]);
            ldsm4(sb + KL_OFF + ao, qfl[kf][0], qfl[kf][1], qfl[kf][2], qfl[kf][3]);
        }
    }

    float oacc[8][4];
#pragma unroll
    for (int i = 0; i < 8; i++)
#pragma unroll
        for (int j = 0; j < 4; j++) oacc[i][j] = 0.0f;
    float rm[2] = {-1e30f, -1e30f};
    float rs[2] = {0.0f, 0.0f};

    const int brow = (lane & 7) + ((lane & 16) >> 1);
    const int bkof = lane & 8;
    const float sc = 0.125f;

    for (int nt = 0; nt <= blockIdx.x; nt++) {
        const int n0 = nt * 64;
        __syncthreads();   // prior tile's smem readers done
#pragma unroll
        for (int it = 0; it < 4; it++) {
            int idx = tid + it * 128;
            int row = idx >> 3, seg = idx & 7;
            uint32_t so = (uint32_t)row * ASR + (uint32_t)seg * 16u;
            size_t g = hb + (size_t)(n0 + row) * Dc + seg * 8;
            CPA16(sb + KH_OFF + so, Kh + g);
            CPA16(sb + KL_OFF + so, Kl + g);
            CPA16(sb + VH_OFF + so, Vh + g);
            CPA16(sb + VL_OFF + so, Vl + g);
        }
        CPCOMMIT();
        CPWAIT(0);
        __syncthreads();

        // ---- S = Q K^T (3-term split, fp32 accum) ----
        float s[8][4];
#pragma unroll
        for (int i = 0; i < 8; i++)
#pragma unroll
            for (int j = 0; j < 4; j++) s[i][j] = 0.0f;
#pragma unroll
        for (int kf = 0; kf < 4; kf++) {
            uint32_t kfh[4][4], kfl[4][4];
            const uint32_t bcb = (uint32_t)(kf * 16 + bkof) * 2u;
#pragma unroll
            for (int ng = 0; ng < 4; ng++) {
                uint32_t bo = (uint32_t)(ng * 16 + brow) * ASR + bcb;
                ldsm4(sb + KH_OFF + bo, kfh[ng][0], kfh[ng][1], kfh[ng][2], kfh[ng][3]);
                ldsm4(sb + KL_OFF + bo, kfl[ng][0], kfl[ng][1], kfl[ng][2], kfl[ng][3]);
            }
#pragma unroll
            for (int nf = 0; nf < 8; nf++) {
                uint32_t fh[2] = {kfh[nf >> 1][(nf & 1) * 2],
                                  kfh[nf >> 1][(nf & 1) * 2 + 1]};
                uint32_t fl[2] = {kfl[nf >> 1][(nf & 1) * 2],
                                  kfl[nf >> 1][(nf & 1) * 2 + 1]};
                mma16816(s[nf], qfh[kf], fh);
                mma16816(s[nf], qfh[kf], fl);
                mma16816(s[nf], qfl[kf], fh);
            }
        }

        // ---- scale + causal mask ----
        if (n0 == m0) {
            const int r0 = m0 + wid * 16 + (lane >> 2);
#pragma unroll
            for (int nf = 0; nf < 8; nf++) {
                const int c0 = n0 + nf * 8 + (lane & 3) * 2;
#pragma unroll
                for (int half = 0; half < 2; half++) {
                    const int row = r0 + half * 8;
                    s[nf][half * 2]     = (c0     <= row) ? s[nf][half * 2] * sc     : -1e30f;
                    s[nf][half * 2 + 1] = (c0 + 1 <= row) ? s[nf][half * 2 + 1] * sc : -1e30f;
                }
            }
        } else {
#pragma unroll
            for (int nf = 0; nf < 8; nf++)
#pragma unroll
                for (int j = 0; j < 4; j++) s[nf][j] *= sc;
        }

        // ---- online softmax (2 rows per thread) ----
        float tmax[2] = {-1e30f, -1e30f};
#pragma unroll
        for (int nf = 0; nf < 8; nf++) {
            tmax[0] = fmaxf(tmax[0], fmaxf(s[nf][0], s[nf][1]));
            tmax[1] = fmaxf(tmax[1], fmaxf(s[nf][2], s[nf][3]));
        }
#pragma unroll
        for (int h = 0; h < 2; h++) {
            tmax[h] = fmaxf(tmax[h], __shfl_xor_sync(0xffffffffu, tmax[h], 1));
            tmax[h] = fmaxf(tmax[h], __shfl_xor_sync(0xffffffffu, tmax[h], 2));
        }
        float nm0 = fmaxf(rm[0], tmax[0]);
        float nm1 = fmaxf(rm[1], tmax[1]);
        float corr0 = __expf(rm[0] - nm0);
        float corr1 = __expf(rm[1] - nm1);
        rm[0] = nm0; rm[1] = nm1;
        float ts0 = 0.0f, ts1 = 0.0f;
#pragma unroll
        for (int nf = 0; nf < 8; nf++) {
            s[nf][0] = __expf(s[nf][0] - nm0); ts0 += s[nf][0];
            s[nf][1] = __expf(s[nf][1] - nm0); ts0 += s[nf][1];
            s[nf][2] = __expf(s[nf][2] - nm1); ts1 += s[nf][2];
            s[nf][3] = __expf(s[nf][3] - nm1); ts1 += s[nf][3];
        }
        ts0 += __shfl_xor_sync(0xffffffffu, ts0, 1);
        ts0 += __shfl_xor_sync(0xffffffffu, ts0, 2);
        ts1 += __shfl_xor_sync(0xffffffffu, ts1, 1);
        ts1 += __shfl_xor_sync(0xffffffffu, ts1, 2);
        rs[0] = rs[0] * corr0 + ts0;
        rs[1] = rs[1] * corr1 + ts1;
#pragma unroll
        for (int df = 0; df < 8; df++) {
            oacc[df][0] *= corr0; oacc[df][1] *= corr0;
            oacc[df][2] *= corr1; oacc[df][3] *= corr1;
        }

        // ---- P frags (hi/lo) ----
        uint32_t pfh[4][4], pfl[4][4];
#pragma unroll
        for (int kf2 = 0; kf2 < 4; kf2++) {
            split_pack(s[2 * kf2][0], s[2 * kf2][1], pfh[kf2][0], pfl[kf2][0]);
            split_pack(s[2 * kf2][2], s[2 * kf2][3], pfh[kf2][1], pfl[kf2][1]);
            split_pack(s[2 * kf2 + 1][0], s[2 * kf2 + 1][1], pfh[kf2][2], pfl[kf2][2]);
            split_pack(s[2 * kf2 + 1][2], s[2 * kf2 + 1][3], pfh[kf2][3], pfl[kf2][3]);
        }

        // ---- O += P V (3-term) ----
#pragma unroll
        for (int df = 0; df < 8; df++) {
#pragma unroll
            for (int kf2 = 0; kf2 < 4; kf2++) {
                uint32_t vo = (uint32_t)(kf2 * 16 + (lane & 15)) * ASR +
                              (uint32_t)df * 16u;
                uint32_t vb[2], vlb[2];
                ldsm2t(sb + VH_OFF + vo, vb[0], vb[1]);
                ldsm2t(sb + VL_OFF + vo, vlb[0], vlb[1]);
                mma16816(oacc[df], pfh[kf2], vb);
                mma16816(oacc[df], pfh[kf2], vlb);
                mma16816(oacc[df], pfl[kf2], vb);
            }
        }
    }

    // ---- epilogue: normalize, split to bf16 hi/lo, write y [B,T,C] ----
    const float inv0 = 1.0f / rs[0];
    const float inv1 = 1.0f / rs[1];
    const int b = bh_i >> 4, h = bh_i & 15;
    const int t0 = m0 + wid * 16 + (lane >> 2);
#pragma unroll
    for (int df = 0; df < 8; df++) {
        const int d = df * 8 + (lane & 3) * 2;
#pragma unroll
        for (int half = 0; half < 2; half++) {
            const int t = t0 + half * 8;
            const float inv = half ? inv1 : inv0;
            float v0 = oacc[df][half * 2] * inv;
            float v1 = oacc[df][half * 2 + 1] * inv;
            uint32_t hiw, low;
            split_pack(v0, v1, hiw, low);
            size_t o = ((size_t)(b * Tc + t)) * Cc + h * Dc + d;
            *(uint32_t*)(Yh + o) = hiw;
            *(uint32_t*)(Yl + o) = low;
        }
    }
}

// ---------------------------------------------------------------------------
extern "C" void kernel_launch(void* const* d_in, const int* in_sizes, int n_in,
                              void* d_out, int out_size) {
    const float* x  = (const float*)d_in[0];
    const float* Wk = (const float*)d_in[1];
    const float* bk = (const float*)d_in[2];
    const float* Wq = (const float*)d_in[3];
    const float* bq = (const float*)d_in[4];
    const float* Wv = (const float*)d_in[5];
    const float* bv = (const float*)d_in[6];
    const float* Wp = (const float*)d_in[7];
    const float* bp = (const float*)d_in[8];
    float* out = (float*)d_out;

    __nv_bfloat16 *xh, *xl, *yh, *yl;
    __nv_bfloat16 *qh, *ql, *kh, *kl, *vh, *vl;
    __nv_bfloat16 *wqh, *wql, *wkh, *wkl, *wvh, *wvl, *wph, *wpl;
    cudaGetSymbolAddress((void**)&xh, g_xh);
    cudaGetSymbolAddress((void**)&xl, g_xl);
    cudaGetSymbolAddress((void**)&yh, g_yh);
    cudaGetSymbolAddress((void**)&yl, g_yl);
    cudaGetSymbolAddress((void**)&qh, g_qh);
    cudaGetSymbolAddress((void**)&ql, g_ql);
    cudaGetSymbolAddress((void**)&kh, g_kh);
    cudaGetSymbolAddress((void**)&kl, g_kl);
    cudaGetSymbolAddress((void**)&vh, g_vh);
    cudaGetSymbolAddress((void**)&vl, g_vl);
    cudaGetSymbolAddress((void**)&wqh, g_wqh);
    cudaGetSymbolAddress((void**)&wql, g_wql);
    cudaGetSymbolAddress((void**)&wkh, g_wkh);
    cudaGetSymbolAddress((void**)&wkl, g_wkl);
    cudaGetSymbolAddress((void**)&wvh, g_wvh);
    cudaGetSymbolAddress((void**)&wvl, g_wvl);
    cudaGetSymbolAddress((void**)&wph, g_wph);
    cudaGetSymbolAddress((void**)&wpl, g_wpl);

    cudaFuncSetAttribute(gemm_mma<0>, cudaFuncAttributeMaxDynamicSharedMemorySize,
                         (int)GEMM_SMEM);
    cudaFuncSetAttribute(gemm_mma<1>, cudaFuncAttributeMaxDynamicSharedMemorySize,
                         (int)GEMM_SMEM);

    // fp32 -> bf16 hi/lo splits (x + weights)
    split_bf16<<<Mtot * Cc / 4 / 256, 256>>>(x, xh, xl);
    split_bf16<<<Cc * Cc / 4 / 256, 256>>>(Wq, wqh, wql);
    split_bf16<<<Cc * Cc / 4 / 256, 256>>>(Wk, wkh, wkl);
    split_bf16<<<Cc * Cc / 4 / 256, 256>>>(Wv, wvh, wvl);
    split_bf16<<<Cc * Cc / 4 / 256, 256>>>(Wp, wph, wpl);

    dim3 ggrid(Cc / 128, Mtot / 128);   // (8, 32)
    gemm_mma<0><<<ggrid, 256, GEMM_SMEM>>>(xh, xl, wqh, wql, bq, qh, ql);
    gemm_mma<0><<<ggrid, 256, GEMM_SMEM>>>(xh, xl, wkh, wkl, bk, kh, kl);
    gemm_mma<0><<<ggrid, 256, GEMM_SMEM>>>(xh, xl, wvh, wvl, bv, vh, vl);

    dim3 agrid(Tc / 64, BHc);           // (32, 32)
    attn_mma<<<agrid, 128, ATTN_SMEM>>>(qh, ql, kh, kl, vh, vl, yh, yl);

    gemm_mma<1><<<ggrid, 256, GEMM_SMEM>>>(yh, yl, wph, wpl, bp, out, nullptr);
}